// round 1
// baseline (speedup 1.0000x reference)
#include <cuda_runtime.h>

#define BB 64
#define TT 8000
#define SS 10
#define CHUNKS 4
#define ROWSPC (TT / CHUNKS)   // 2000 rows per chunk-block
#define NACC 110               // 100 sel + 10 tot
#define NW 8                   // warps per block in hungarian kernel

// Scratch (no allocations allowed): per-(batch,chunk) partial sums + per-batch matched sums.
__device__ float  g_part[BB * CHUNKS * NACC];
__device__ double g_bsum[BB];

// ---------------------------------------------------------------------------
// Kernel 1: pairwise BCE partial reduction.
// grid = BB*CHUNKS blocks, 256 threads. Block (b,c) reduces rows [c*2000, (c+1)*2000)
// of batch b into g_part[(b*CHUNKS+c)*NACC + k]  (k<100: sel[i*10+j], k>=100: tot[i]).
// ---------------------------------------------------------------------------
__global__ __launch_bounds__(256) void pairwise_kernel(const float* __restrict__ pred,
                                                       const float* __restrict__ tgt) {
    const int b   = blockIdx.x / CHUNKS;
    const int c   = blockIdx.x % CHUNKS;
    const int tid = threadIdx.x;

    float sel[SS][SS];
    float tot[SS];
#pragma unroll
    for (int i = 0; i < SS; i++) {
        tot[i] = 0.0f;
#pragma unroll
        for (int j = 0; j < SS; j++) sel[i][j] = 0.0f;
    }

    const int t0 = c * ROWSPC;
    for (int t = t0 + tid; t < t0 + ROWSPC; t += 256) {
        const size_t base = ((size_t)b * TT + (size_t)t) * SS;
        const float2* pp = reinterpret_cast<const float2*>(pred + base);
        const float2* tp = reinterpret_cast<const float2*>(tgt + base);
        float pv[SS], tv[SS];
#pragma unroll
        for (int q = 0; q < 5; q++) { float2 x = pp[q]; pv[2*q] = x.x; pv[2*q+1] = x.y; }
#pragma unroll
        for (int q = 0; q < 5; q++) { float2 x = tp[q]; tv[2*q] = x.x; tv[2*q+1] = x.y; }

        float diff[SS];
#pragma unroll
        for (int i = 0; i < SS; i++) {
            float l1 = __logf(pv[i]);            // log(p)
            float l2 = __logf(1.0f - pv[i]);     // log1p(-p); p in [0.01,0.99] so exact enough
            diff[i] = l1 - l2;
            tot[i] += l2;
        }
#pragma unroll
        for (int j = 0; j < SS; j++) {
            const float tj = tv[j];              // exactly 0.0f or 1.0f
#pragma unroll
            for (int i = 0; i < SS; i++)
                sel[i][j] = fmaf(diff[i], tj, sel[i][j]);
        }
    }

    // Warp-level tree reduction of all 110 accumulators.
#pragma unroll
    for (int i = 0; i < SS; i++) {
#pragma unroll
        for (int j = 0; j < SS; j++) {
            float v = sel[i][j];
#pragma unroll
            for (int o = 16; o; o >>= 1) v += __shfl_down_sync(0xFFFFFFFFu, v, o);
            sel[i][j] = v;
        }
        float v = tot[i];
#pragma unroll
        for (int o = 16; o; o >>= 1) v += __shfl_down_sync(0xFFFFFFFFu, v, o);
        tot[i] = v;
    }

    __shared__ float s[8][NACC];
    const int w = tid >> 5, lane = tid & 31;
    if (lane == 0) {
#pragma unroll
        for (int i = 0; i < SS; i++) {
#pragma unroll
            for (int j = 0; j < SS; j++) s[w][i * SS + j] = sel[i][j];
            s[w][100 + i] = tot[i];
        }
    }
    __syncthreads();
    if (tid < NACC) {
        float v = 0.0f;
#pragma unroll
        for (int ww = 0; ww < 8; ww++) v += s[ww][tid];
        g_part[(b * CHUNKS + c) * NACC + tid] = v;   // deterministic: fixed slot, no atomics
    }
}

// ---------------------------------------------------------------------------
// Kernel 2: warp-per-batch Hungarian (Jonker-Volgenant, n=10), f64 like reference.
// Lanes 1..10 own columns; min over unused columns via shfl_xor reduce (16-lane tree).
// ---------------------------------------------------------------------------
__global__ __launch_bounds__(NW * 32) void hungarian_kernel() {
    __shared__ double s_cost[NW][SS][SS];
    __shared__ double s_u[NW][SS + 1], s_v[NW][SS + 1], s_minv[NW][SS + 1];
    __shared__ int    s_p[NW][SS + 1], s_way[NW][SS + 1], s_used[NW][SS + 1];

    const int w    = threadIdx.x >> 5;
    const int lane = threadIdx.x & 31;
    const int b    = blockIdx.x * NW + w;
    const int n    = SS;

    // Build cost (float math to match reference's f32 pairwise, then f64 for assignment).
    for (int k = lane; k < 100; k += 32) {
        const int i = k / 10, j = k % 10;
        float sl = 0.0f, to = 0.0f;
#pragma unroll
        for (int c = 0; c < CHUNKS; c++) {
            const float* gp = &g_part[(b * CHUNKS + c) * NACC];
            sl += gp[k];
            to += gp[100 + i];
        }
        s_cost[w][i][j] = (double)(-(to + sl) * (1.0f / (float)TT));
    }
    if (lane <= n) { s_u[w][lane] = 0.0; s_v[w][lane] = 0.0; s_p[w][lane] = 0; s_way[w][lane] = 0; }
    __syncwarp();

    for (int i = 1; i <= n; i++) {
        if (lane == 0) s_p[w][0] = i;
        if (lane <= n) { s_minv[w][lane] = 1e300; s_used[w][lane] = 0; }
        __syncwarp();
        int j0 = 0;
        while (true) {
            if (lane == 0) s_used[w][j0] = 1;
            __syncwarp();
            const int    i0 = s_p[w][j0];
            const double u0 = s_u[w][i0];

            double cand = 1e300;
            if (lane >= 1 && lane <= n && !s_used[w][lane]) {
                double cur = s_cost[w][i0 - 1][lane - 1] - u0 - s_v[w][lane];
                if (cur < s_minv[w][lane]) { s_minv[w][lane] = cur; s_way[w][lane] = j0; }
                cand = s_minv[w][lane];
            }
            // (min, argmin-lowest-index) reduce over lanes 0..15 (lanes 11..15 hold +inf).
            double delta = cand; int j1 = lane;
#pragma unroll
            for (int o = 8; o; o >>= 1) {
                double od = __shfl_xor_sync(0xFFFFFFFFu, delta, o);
                int    oj = __shfl_xor_sync(0xFFFFFFFFu, j1, o);
                if (od < delta || (od == delta && oj < j1)) { delta = od; j1 = oj; }
            }
            delta = __shfl_sync(0xFFFFFFFFu, delta, 0);
            j1    = __shfl_sync(0xFFFFFFFFu, j1, 0);

            if (lane <= n) {
                if (s_used[w][lane]) {
                    s_u[w][s_p[w][lane]] += delta;   // distinct targets across used lanes
                    s_v[w][lane]         -= delta;
                } else {
                    s_minv[w][lane] -= delta;
                }
            }
            __syncwarp();
            j0 = j1;
            if (s_p[w][j0] == 0) break;
        }
        if (lane == 0) {
            while (j0) { int jprev = s_way[w][j0]; s_p[w][j0] = s_p[w][jprev]; j0 = jprev; }
        }
        __syncwarp();
    }

    // Matched sum: column j is assigned row p[j]-1.
    double val = 0.0;
    if (lane >= 1 && lane <= n) val = s_cost[w][s_p[w][lane] - 1][lane - 1];
#pragma unroll
    for (int o = 16; o; o >>= 1) val += __shfl_down_sync(0xFFFFFFFFu, val, o);
    if (lane == 0) g_bsum[b] = val;   // deterministic per-batch slot
}

// ---------------------------------------------------------------------------
// Kernel 3: final mean over B*S matched entries -> scalar f32.
// ---------------------------------------------------------------------------
__global__ void finalize_kernel(float* __restrict__ out) {
    __shared__ double s2[2];
    const int tid = threadIdx.x;
    double v = g_bsum[tid];            // 64 threads, 2 warps
#pragma unroll
    for (int o = 16; o; o >>= 1) v += __shfl_down_sync(0xFFFFFFFFu, v, o);
    if ((tid & 31) == 0) s2[tid >> 5] = v;
    __syncthreads();
    if (tid == 0) out[0] = (float)((s2[0] + s2[1]) / (double)(BB * SS));
}

extern "C" void kernel_launch(void* const* d_in, const int* in_sizes, int n_in,
                              void* d_out, int out_size) {
    const float* pred = (const float*)d_in[0];
    const float* tgt  = (const float*)d_in[1];
    pairwise_kernel<<<BB * CHUNKS, 256>>>(pred, tgt);
    hungarian_kernel<<<BB / NW, NW * 32>>>();
    finalize_kernel<<<1, 64>>>((float*)d_out);
}

// round 2
// speedup vs baseline: 2.5825x; 2.5825x over previous
#include <cuda_runtime.h>

#define BB 64
#define TT 8000
#define SS 10
#define CHUNKS 4
#define ROWSPC (TT / CHUNKS)   // 2000 rows per chunk-block
#define NACC 110               // 100 sel + 10 tot
#define FULL 0xFFFFFFFFu

// Scratch (no allocations allowed): per-(batch,chunk) partial sums + per-batch matched sums.
__device__ float  g_part[BB * CHUNKS * NACC];
__device__ double g_bsum[BB];

// ---------------------------------------------------------------------------
// Kernel 1: pairwise BCE partial reduction, i-dimension split across thread
// pairs. Thread pair (2s, 2s+1) covers row-slot s; even thread handles
// i=0..4, odd thread i=5..9. 55 accumulators/thread -> ~2 blocks/SM.
// ---------------------------------------------------------------------------
__global__ __launch_bounds__(256, 2) void pairwise_kernel(const float* __restrict__ pred,
                                                          const float* __restrict__ tgt) {
    const int b    = blockIdx.x / CHUNKS;
    const int c    = blockIdx.x % CHUNKS;
    const int tid  = threadIdx.x;
    const int half = tid & 1;           // 0: i=0..4, 1: i=5..9
    const int slot = tid >> 1;          // 0..127

    float sel[5][SS];
    float tot[5];
#pragma unroll
    for (int ii = 0; ii < 5; ii++) {
        tot[ii] = 0.0f;
#pragma unroll
        for (int j = 0; j < SS; j++) sel[ii][j] = 0.0f;
    }

    const int t0   = c * ROWSPC;
    const int tend = t0 + ROWSPC;
    const int ibase = half * 5;

    for (int t = t0 + slot; t < tend; t += 128) {
        const size_t base = ((size_t)b * TT + (size_t)t) * SS;
        const float2* pp = reinterpret_cast<const float2*>(pred + base);
        const float2* tp = reinterpret_cast<const float2*>(tgt + base);
        float pv[SS], tv[SS];
#pragma unroll
        for (int q = 0; q < 5; q++) { float2 x = pp[q]; pv[2*q] = x.x; pv[2*q+1] = x.y; }
#pragma unroll
        for (int q = 0; q < 5; q++) { float2 x = tp[q]; tv[2*q] = x.x; tv[2*q+1] = x.y; }

        float diff[5];
#pragma unroll
        for (int ii = 0; ii < 5; ii++) {
            const float p  = pv[ibase + ii];
            const float l1 = __logf(p);            // log(p)
            const float l2 = __logf(1.0f - p);     // log1p(-p); p in [0.01, 0.99]
            diff[ii] = l1 - l2;
            tot[ii] += l2;
        }
#pragma unroll
        for (int j = 0; j < SS; j++) {
            const float tj = tv[j];                // exactly 0.0f or 1.0f
#pragma unroll
            for (int ii = 0; ii < 5; ii++)
                sel[ii][j] = fmaf(diff[ii], tj, sel[ii][j]);
        }
    }

    // Parity-preserving warp tree reduce (offsets 16,8,4,2): lane0 sums the
    // even lanes (i=0..4 block), lane1 sums the odd lanes (i=5..9 block).
#pragma unroll
    for (int ii = 0; ii < 5; ii++) {
#pragma unroll
        for (int j = 0; j < SS; j++) {
            float v = sel[ii][j];
#pragma unroll
            for (int o = 16; o >= 2; o >>= 1) v += __shfl_down_sync(FULL, v, o);
            sel[ii][j] = v;
        }
        float v = tot[ii];
#pragma unroll
        for (int o = 16; o >= 2; o >>= 1) v += __shfl_down_sync(FULL, v, o);
        tot[ii] = v;
    }

    __shared__ float s[8][NACC];
    const int w = tid >> 5, lane = tid & 31;
    if (lane < 2) {
        const int off = lane * 50;     // lane0 -> i=0..4, lane1 -> i=5..9
#pragma unroll
        for (int ii = 0; ii < 5; ii++) {
#pragma unroll
            for (int j = 0; j < SS; j++) s[w][off + ii * SS + j] = sel[ii][j];
            s[w][100 + lane * 5 + ii] = tot[ii];
        }
    }
    __syncthreads();
    if (tid < NACC) {
        float v = 0.0f;
#pragma unroll
        for (int ww = 0; ww < 8; ww++) v += s[ww][tid];
        g_part[(b * CHUNKS + c) * NACC + tid] = v;   // deterministic: fixed slot
    }
}

// ---------------------------------------------------------------------------
// Kernel 2: warp-per-batch Hungarian (Jonker-Volgenant, n=10), f32, state in
// lane registers. Lane j (0..10) owns p/way/v/minv for column j; lane i owns
// u[i]; used-columns and covered-rows are uniform bitmasks. No __syncwarp in
// the inner loop; min+argmin via REDUX.MIN.U32 + ballot.
// ---------------------------------------------------------------------------
__device__ __forceinline__ unsigned enc_f32(float x) {
    unsigned b = __float_as_uint(x);
    return (b & 0x80000000u) ? ~b : (b | 0x80000000u);
}
__device__ __forceinline__ float dec_f32(unsigned e) {
    unsigned b = (e & 0x80000000u) ? (e & 0x7FFFFFFFu) : ~e;
    return __uint_as_float(b);
}

__global__ __launch_bounds__(32) void hungarian_kernel() {
    __shared__ float s_cost[SS][SS];
    const int lane = threadIdx.x;
    const int b    = blockIdx.x;
    const int n    = SS;

    // Build f32 cost matrix (matches the reference's f32 pairwise values).
    for (int k = lane; k < 100; k += 32) {
        const int i = k / 10, j = k % 10;
        float sl = 0.0f, to = 0.0f;
#pragma unroll
        for (int c = 0; c < CHUNKS; c++) {
            const float* gp = &g_part[(b * CHUNKS + c) * NACC];
            sl += gp[k];
            to += gp[100 + i];
        }
        s_cost[i][j] = -(to + sl) * (1.0f / (float)TT);
    }
    __syncwarp();

    // Lane-register state.
    int   p = 0, way = 0;     // lane j: column j's assigned row / alternating path
    float v = 0.0f;           // lane j: potential of column j
    float u = 0.0f;           // lane i: potential of row i (i = 1..10)
    float minv;

    for (int i = 1; i <= n; i++) {
        if (lane == 0) p = i;
        minv = 3.402823466e+38f;            // FLT_MAX
        unsigned used_mask = 0u, row_mask = 0u;
        int j0 = 0;

        while (true) {
            used_mask |= 1u << j0;
            const int   i0 = __shfl_sync(FULL, p, j0);
            row_mask |= 1u << i0;
            const float u0 = __shfl_sync(FULL, u, i0);

            const bool active = (lane >= 1) && (lane <= n) && !((used_mask >> lane) & 1u);
            if (active) {
                const float cur = s_cost[i0 - 1][lane - 1] - u0 - v;
                if (cur < minv) { minv = cur; way = j0; }
            }
            const unsigned key = active ? enc_f32(minv) : 0xFFFFFFFFu;
            const unsigned m   = __reduce_min_sync(FULL, key);
            const unsigned bal = __ballot_sync(FULL, key == m);
            const int      j1  = __ffs(bal) - 1;   // lowest j among minima (ref tie-break)
            const float delta  = dec_f32(m);

            if (lane <= n) {
                if ((used_mask >> lane) & 1u) v -= delta;
                else                          minv -= delta;
            }
            if ((row_mask >> lane) & 1u) u += delta;

            j0 = j1;
            if (__shfl_sync(FULL, p, j0) == 0) break;
        }

        // Augment along the alternating path (uniform j0, register scatter).
        while (j0) {
            const int jprev = __shfl_sync(FULL, way, j0);
            const int pprev = __shfl_sync(FULL, p, jprev);
            if (lane == j0) p = pprev;
            j0 = jprev;
        }
    }

    // Matched sum: column j is assigned row p[j]-1. Sum in f64 for the mean.
    double val = 0.0;
    if (lane >= 1 && lane <= n) val = (double)s_cost[p - 1][lane - 1];
#pragma unroll
    for (int o = 16; o; o >>= 1) val += __shfl_down_sync(FULL, val, o);
    if (lane == 0) g_bsum[b] = val;
}

// ---------------------------------------------------------------------------
// Kernel 3: final mean over B*S matched entries -> scalar f32.
// ---------------------------------------------------------------------------
__global__ void finalize_kernel(float* __restrict__ out) {
    __shared__ double s2[2];
    const int tid = threadIdx.x;
    double v = g_bsum[tid];            // 64 threads, 2 warps
#pragma unroll
    for (int o = 16; o; o >>= 1) v += __shfl_down_sync(FULL, v, o);
    if ((tid & 31) == 0) s2[tid >> 5] = v;
    __syncthreads();
    if (tid == 0) out[0] = (float)((s2[0] + s2[1]) / (double)(BB * SS));
}

extern "C" void kernel_launch(void* const* d_in, const int* in_sizes, int n_in,
                              void* d_out, int out_size) {
    const float* pred = (const float*)d_in[0];
    const float* tgt  = (const float*)d_in[1];
    pairwise_kernel<<<BB * CHUNKS, 256>>>(pred, tgt);
    hungarian_kernel<<<BB, 32>>>();
    finalize_kernel<<<1, 64>>>((float*)d_out);
}

// round 3
// speedup vs baseline: 2.8564x; 1.1061x over previous
#include <cuda_runtime.h>

#define BB 64
#define TT 8000
#define SS 10
#define CHUNKS 9
#define ROWSPC ((TT + CHUNKS - 1) / CHUNKS)   // 889
#define NACC 110                              // 100 sel + 10 tot
#define FULL 0xFFFFFFFFu
#define FLT_MAX_C 3.402823466e+38f

// Scratch (no allocations allowed).
__device__ float    g_part[BB * CHUNKS * NACC];
__device__ double   g_bsum[BB];
__device__ unsigned g_ticket = 0;

// ---------------------------------------------------------------------------
// Kernel 1: pairwise BCE partial reduction.
// 576 blocks x 256 threads, 4 blocks/SM (50% occ). Each warp owns one
// (ihalf, jhalf) class of the 10x10 outer product: thread accumulates
// sel[5][5] + tot[5] (30 regs). slot = tid & 63 strides the chunk's rows;
// warps 2q,2q+1 together cover every row once for class q.
// ---------------------------------------------------------------------------
template <int IH, int JH>
__device__ __forceinline__ void pw_body(const float* __restrict__ pred,
                                        const float* __restrict__ tgt,
                                        int b, int t0, int tend, int slot,
                                        float sel[5][5], float tot[5]) {
    for (int t = t0 + slot; t < tend; t += 64) {
        const size_t base = ((size_t)b * TT + (size_t)t) * SS;
        // 6-element windows: elements [IH*4, IH*4+6) cover [IH*5, IH*5+5).
        const float2* pp = reinterpret_cast<const float2*>(pred + base + IH * 4);
        const float2* tp = reinterpret_cast<const float2*>(tgt  + base + JH * 4);
        const float2 p0 = pp[0], p1 = pp[1], p2 = pp[2];
        const float2 q0 = tp[0], q1 = tp[1], q2 = tp[2];
        const float pe[6] = {p0.x, p0.y, p1.x, p1.y, p2.x, p2.y};
        const float te[6] = {q0.x, q0.y, q1.x, q1.y, q2.x, q2.y};

        float diff[5];
#pragma unroll
        for (int ii = 0; ii < 5; ii++) {
            const float p  = pe[ii + IH];          // static index
            const float l1 = __logf(p);            // log(p)
            const float l2 = __logf(1.0f - p);     // log1p(-p); p in [0.01, 0.99]
            diff[ii] = l1 - l2;
            tot[ii] += l2;
        }
#pragma unroll
        for (int jj = 0; jj < 5; jj++) {
            const float tj = te[jj + JH];          // exactly 0.0f or 1.0f
#pragma unroll
            for (int ii = 0; ii < 5; ii++)
                sel[ii][jj] = fmaf(diff[ii], tj, sel[ii][jj]);
        }
    }
}

__global__ __launch_bounds__(256, 4) void pairwise_kernel(const float* __restrict__ pred,
                                                          const float* __restrict__ tgt) {
    const int b    = blockIdx.x / CHUNKS;
    const int c    = blockIdx.x % CHUNKS;
    const int tid  = threadIdx.x;
    const int slot = tid & 63;
    const int w    = tid >> 5;
    const int q    = w >> 1;                  // warp-uniform class: ihalf = q&1, jhalf = q>>1

    const int t0   = c * ROWSPC;
    const int tend = (t0 + ROWSPC < TT) ? (t0 + ROWSPC) : TT;

    float sel[5][5];
    float tot[5];
#pragma unroll
    for (int ii = 0; ii < 5; ii++) {
        tot[ii] = 0.0f;
#pragma unroll
        for (int jj = 0; jj < 5; jj++) sel[ii][jj] = 0.0f;
    }

    switch (q) {
        case 0: pw_body<0, 0>(pred, tgt, b, t0, tend, slot, sel, tot); break;
        case 1: pw_body<1, 0>(pred, tgt, b, t0, tend, slot, sel, tot); break;
        case 2: pw_body<0, 1>(pred, tgt, b, t0, tend, slot, sel, tot); break;
        default: pw_body<1, 1>(pred, tgt, b, t0, tend, slot, sel, tot); break;
    }

    // Full-warp tree reduction of the 30 accumulators -> lane 0.
#pragma unroll
    for (int ii = 0; ii < 5; ii++) {
#pragma unroll
        for (int jj = 0; jj < 5; jj++) {
            float v = sel[ii][jj];
#pragma unroll
            for (int o = 16; o; o >>= 1) v += __shfl_down_sync(FULL, v, o);
            sel[ii][jj] = v;
        }
        float v = tot[ii];
#pragma unroll
        for (int o = 16; o; o >>= 1) v += __shfl_down_sync(FULL, v, o);
        tot[ii] = v;
    }

    __shared__ float s[8][30];
    const int lane = tid & 31;
    if (lane == 0) {
#pragma unroll
        for (int ii = 0; ii < 5; ii++) {
#pragma unroll
            for (int jj = 0; jj < 5; jj++) s[w][ii * 5 + jj] = sel[ii][jj];
            s[w][25 + ii] = tot[ii];
        }
    }
    __syncthreads();

    if (tid < NACC) {
        int qq, idx;
        if (tid < 100) {
            const int i = tid / 10, j = tid % 10;
            const int ih = (i >= 5), jh = (j >= 5);
            qq  = jh * 2 + ih;
            idx = (i % 5) * 5 + (j % 5);
        } else {
            const int i = tid - 100;
            const int ih = (i >= 5);
            qq  = ih;                      // tot kept only by jhalf==0 classes
            idx = 25 + (i % 5);
        }
        g_part[(b * CHUNKS + c) * NACC + tid] = s[2 * qq][idx] + s[2 * qq + 1][idx];
    }
}

// ---------------------------------------------------------------------------
// Kernel 2: warp-per-batch Hungarian (Jonker-Volgenant, n=10) + fused final
// reduction. Lane j owns p/way/v/minv/u[p[j]] for column j; lane i owns u[i].
// Min+argmin = one REDUX.MIN.U32 on a packed (float-key | lane) word.
// ---------------------------------------------------------------------------
__device__ __forceinline__ unsigned enc_f32(float x) {
    unsigned b = __float_as_uint(x);
    return (b & 0x80000000u) ? ~b : (b | 0x80000000u);
}

__global__ __launch_bounds__(32) void hungarian_kernel(float* __restrict__ out) {
    __shared__ float s_cost[100];
    const int lane = threadIdx.x;
    const int b    = blockIdx.x;

    // Build f32 cost matrix from chunk partials.
    for (int k = lane; k < 100; k += 32) {
        const int i = k / 10;
        float sl = 0.0f, to = 0.0f;
#pragma unroll
        for (int c = 0; c < CHUNKS; c++) {
            const float* gp = &g_part[(b * CHUNKS + c) * NACC];
            sl += gp[k];
            to += gp[100 + i];
        }
        s_cost[k] = -(to + sl) * (1.0f / (float)TT);
    }
    __syncwarp();

    const int cl = (lane >= 1 && lane <= SS) ? (lane - 1) : 0;  // safe smem column

    int   p = 0, way = 0;   // lane j: assigned row of column j / alternating path
    float v = 0.0f;         // lane j: column potential
    float u = 0.0f;         // lane i: row potential
    float minv, upj;

    for (int root = 1; root <= SS; root++) {
        if (lane == 0) p = root;
        upj  = __shfl_sync(FULL, u, p & 31);     // u[p[j]] (garbage where p==0, unused)
        minv = FLT_MAX_C;
        unsigned used = 0u, rowm = 0u;
        int   j0 = 0;
        int   i0 = root;
        float u0 = __shfl_sync(FULL, u, root);

        while (true) {
            used |= 1u << j0;
            rowm |= 1u << i0;

            const bool  active = (lane >= 1) && (lane <= SS) && !((used >> lane) & 1u);
            const float cur    = s_cost[(i0 - 1) * 10 + cl] - u0 - v;
            if (active && cur < minv) { minv = cur; way = j0; }

            const unsigned key = active ? ((enc_f32(minv) & 0xFFFFFFE0u) | (unsigned)lane)
                                        : 0xFFFFFFFFu;
            const unsigned m   = __reduce_min_sync(FULL, key);
            const int      j1  = (int)(m & 31u);           // lowest j among minima
            const float delta  = __shfl_sync(FULL, minv, j1);   // exact winner value
            const int   pn     = __shfl_sync(FULL, p, j1);      // next i0 (0 = free col)
            const float u0n    = __shfl_sync(FULL, upj, j1);    // u[pn] (row uncovered)

            if (lane <= SS) {
                if ((used >> lane) & 1u) v -= delta;
                else                     minv -= delta;
            }
            if ((used >> lane) & 1u) upj += delta;
            if ((rowm >> lane) & 1u) u   += delta;

            j0 = j1; i0 = pn; u0 = u0n;
            if (pn == 0) break;
        }

        // Augment along the alternating path.
        while (j0) {
            const int jprev = __shfl_sync(FULL, way, j0);
            const int pprev = __shfl_sync(FULL, p, jprev);
            if (lane == j0) p = pprev;
            j0 = jprev;
        }
    }

    // Matched sum for this batch (exact f32 cost entries, f64 accumulate).
    double val = 0.0;
    if (lane >= 1 && lane <= SS) val = (double)s_cost[(p - 1) * 10 + cl];
#pragma unroll
    for (int o = 16; o; o >>= 1) val += __shfl_down_sync(FULL, val, o);
    if (lane == 0) g_bsum[b] = val;

    // Fused finalize: last block reduces all 64 batch sums.
    __threadfence();
    unsigned ticket = 0;
    if (lane == 0) ticket = atomicAdd(&g_ticket, 1u);
    ticket = __shfl_sync(FULL, ticket, 0);
    if (ticket == BB - 1) {
        double x = __ldcg(&g_bsum[lane]) + __ldcg(&g_bsum[lane + 32]);
#pragma unroll
        for (int o = 16; o; o >>= 1) x += __shfl_down_sync(FULL, x, o);
        if (lane == 0) {
            out[0]   = (float)(x / (double)(BB * SS));
            g_ticket = 0;                          // reset for graph replay
        }
    }
}

extern "C" void kernel_launch(void* const* d_in, const int* in_sizes, int n_in,
                              void* d_out, int out_size) {
    const float* pred = (const float*)d_in[0];
    const float* tgt  = (const float*)d_in[1];
    pairwise_kernel<<<BB * CHUNKS, 256>>>(pred, tgt);
    hungarian_kernel<<<BB, 32>>>((float*)d_out);
}